// round 16
// baseline (speedup 1.0000x reference)
#include <cuda_runtime.h>
#include <cuda_fp16.h>
#include <cstdint>

#define BATCH 256
#define OUTF  1024
#define INF   1024

// ---------------- device scratch (no allocs allowed) ----------------
// chunk-major, unit-swizzled fp16 copies: [kchunk][row][128 fp16],
// 16B unit u stored at u ^ (row & 7) so a verbatim bulk copy lands
// bank-conflict-free for ldmatrix.
__device__ int g_flag = 0;   // monotonic: 0 = fast path valid
__device__ __half g_phi_c[BATCH * INF];
__device__ __half g_w_c[OUTF * INF];

// ---------------- helpers ----------------
__device__ __forceinline__ uint32_t smem_u32(const void* p) {
    uint32_t a;
    asm("{ .reg .u64 t; cvta.to.shared.u64 t, %1; cvt.u32.u64 %0, t; }"
        : "=r"(a) : "l"(p));
    return a;
}

#define MBARRIER_INIT(addr, cnt)                                                \
    asm volatile("mbarrier.init.shared.b64 [%0], %1;"                           \
                 :: "r"(addr), "r"((uint32_t)(cnt)) : "memory")

#define MBARRIER_EXPECT_TX(addr, bytes)                                         \
    asm volatile("mbarrier.arrive.expect_tx.shared.b64 _, [%0], %1;"            \
                 :: "r"(addr), "r"((uint32_t)(bytes)) : "memory")

#define MBARRIER_WAIT_PARITY(addr, parity) do {                                 \
    uint32_t _m = (uint32_t)(addr);                                             \
    uint32_t _p = (uint32_t)(parity);                                           \
    asm volatile(                                                               \
        "{\n\t.reg .pred P1;\n\t"                                               \
        "WL_%=:\n\t"                                                            \
        "mbarrier.try_wait.parity.acquire.cta.shared::cta.b64 P1, [%0], %1, 0x989680;\n\t" \
        "@P1 bra.uni WD_%=;\n\t"                                                \
        "bra.uni WL_%=;\n\t"                                                    \
        "WD_%=:\n\t}"                                                           \
        :: "r"(_m), "r"(_p) : "memory");                                        \
} while (0)

__device__ __forceinline__ void bulk_g2s(uint32_t dst, const void* src,
                                         uint32_t bytes, uint32_t mbar) {
    asm volatile(
        "cp.async.bulk.shared::cluster.global.mbarrier::complete_tx::bytes "
        "[%0], [%1], %2, [%3];"
        :: "r"(dst), "l"(src), "r"(bytes), "r"(mbar) : "memory");
}

__device__ __forceinline__ void ldm_x4(uint32_t& r0, uint32_t& r1,
                                       uint32_t& r2, uint32_t& r3,
                                       uint32_t addr) {
    asm volatile("ldmatrix.sync.aligned.m8n8.x4.shared.b16 {%0,%1,%2,%3}, [%4];"
                 : "=r"(r0), "=r"(r1), "=r"(r2), "=r"(r3) : "r"(addr));
}

__device__ __forceinline__ void mma16816(float* c, const uint32_t* a,
                                         const uint32_t* b) {
    asm volatile(
        "mma.sync.aligned.m16n8k16.row.col.f32.f16.f16.f32 "
        "{%0,%1,%2,%3}, {%4,%5,%6,%7}, {%8,%9}, {%0,%1,%2,%3};"
        : "+f"(c[0]), "+f"(c[1]), "+f"(c[2]), "+f"(c[3])
        : "r"(a[0]), "r"(a[1]), "r"(a[2]), "r"(a[3]), "r"(b[0]), "r"(b[1]));
}

// pack 8 floats -> uint4 of fp16 (rn)
__device__ __forceinline__ uint4 pack8_h(const float4& a, const float4& b) {
    __half2 h0 = __floats2half2_rn(a.x, a.y);
    __half2 h1 = __floats2half2_rn(a.z, a.w);
    __half2 h2 = __floats2half2_rn(b.x, b.y);
    __half2 h3 = __floats2half2_rn(b.z, b.w);
    return make_uint4(*(uint32_t*)&h0, *(uint32_t*)&h1,
                      *(uint32_t*)&h2, *(uint32_t*)&h3);
}

__device__ __forceinline__ float dog(float x, float t, float s) {
    float z = (x - t) / s;
    return -z * __expf(-0.5f * z * z);
}

// ---------------- fused prep: check + W/phi -> fp16 chunk-major ----------
#define W_BLOCKS   ((OUTF * INF / 8) / 256)    // 512
#define PHI_BLOCKS ((BATCH * INF / 8) / 256)   // 128

__global__ __launch_bounds__(256)
void prep_kernel(const float4* __restrict__ w,
                 const float4* __restrict__ x,
                 const float4* __restrict__ scale,
                 const float4* __restrict__ trans) {
    if (blockIdx.x < W_BLOCKS) {
        int tix = blockIdx.x * 256 + threadIdx.x;   // 0..131071, 8 elems each
        int j = tix * 2;                             // even float4 index
        int i40 = j & (INF / 4 - 1);
        int i41 = (j + 1) & (INF / 4 - 1);

        float4 w0 = w[j],     w1 = w[j + 1];
        float4 s0 = scale[j], s1 = scale[j + 1];
        float4 t0 = trans[j], t1 = trans[j + 1];
        float4 rs0 = scale[i40], rs1 = scale[i41];
        float4 rt0 = trans[i40], rt1 = trans[i41];

        bool bad =
            (s0.x != rs0.x) | (s0.y != rs0.y) | (s0.z != rs0.z) | (s0.w != rs0.w) |
            (s1.x != rs1.x) | (s1.y != rs1.y) | (s1.z != rs1.z) | (s1.w != rs1.w) |
            (t0.x != rt0.x) | (t0.y != rt0.y) | (t0.z != rt0.z) | (t0.w != rt0.w) |
            (t1.x != rt1.x) | (t1.y != rt1.y) | (t1.z != rt1.z) | (t1.w != rt1.w);
        if (bad) atomicOr(&g_flag, 1);

        int o = tix >> 7;             // row 0..1023
        int ug = tix & 127;           // 16B unit within row (global k)
        int chunk = ug >> 4;          // k-chunk 0..7
        int u = ug & 15;              // unit within chunk
        int dst = (chunk * OUTF + o) * 16 + (u ^ (o & 7));
        reinterpret_cast<uint4*>(g_w_c)[dst] = pack8_h(w0, w1);
    } else {
        int tix = (blockIdx.x - W_BLOCKS) * 256 + threadIdx.x;  // 0..32767
        int j = tix * 2;
        int i40 = j & (INF / 4 - 1);
        int i41 = (j + 1) & (INF / 4 - 1);
        float4 x0 = x[j], x1 = x[j + 1];
        float4 s0 = scale[i40], s1 = scale[i41];
        float4 t0 = trans[i40], t1 = trans[i41];
        float4 p0, p1;
        p0.x = dog(x0.x, t0.x, s0.x);
        p0.y = dog(x0.y, t0.y, s0.y);
        p0.z = dog(x0.z, t0.z, s0.z);
        p0.w = dog(x0.w, t0.w, s0.w);
        p1.x = dog(x1.x, t1.x, s1.x);
        p1.y = dog(x1.y, t1.y, s1.y);
        p1.z = dog(x1.z, t1.z, s1.z);
        p1.w = dog(x1.w, t1.w, s1.w);

        int m = tix >> 7;             // row 0..255
        int ug = tix & 127;
        int chunk = ug >> 4;
        int u = ug & 15;
        int dst = (chunk * BATCH + m) * 16 + (u ^ (m & 7));
        reinterpret_cast<uint4*>(g_phi_c)[dst] = pack8_h(p0, p1);
    }
}

// ---------------- fp16 mma.sync GEMM, bulk-copy loads ----------------
// out(256,1024) = phi @ W^T. CTA tile 32x64, 256 threads (8 warps, 2m x 4n),
// warp tile 16x16. BK=128 -> 8 chunks, 3-stage, cp.async.bulk + mbarrier.
#define BM 32
#define BN 64
#define BK 128
#define NCHUNK (INF / BK)            // 8
#define ROWB    256                  // 128 fp16, no pad (XOR swizzle instead)
#define A_TILE  (BM * ROWB)          // 8192
#define B_TILE  (BN * ROWB)          // 16384
#define STAGEB  (A_TILE + B_TILE)    // 24576
#define NSTAGE  3
#define SMEM_STAGE0 1024
#define GEMM_SMEM (SMEM_STAGE0 + NSTAGE * STAGEB)   // 74752

// swizzled smem address for 16B-aligned (row, kElem) within a tile
__device__ __forceinline__ uint32_t swz(uint32_t base, int row, int kElem) {
    return base + row * ROWB + (((kElem >> 3) ^ (row & 7)) << 4);
}

__global__ __launch_bounds__(256, 1)
void mma_gemm_kernel(float* __restrict__ out,
                     const float* __restrict__ x,
                     const float* __restrict__ w,
                     const float* __restrict__ s,
                     const float* __restrict__ t) {
    const int tid = threadIdx.x;
    const int m0 = blockIdx.y * BM;
    const int n0 = blockIdx.x * BN;

    if (g_flag) {
        // exact general path: 8 outputs per thread
        for (int e = tid; e < BM * BN; e += 256) {
            int b = m0 + (e >> 6);
            int o = n0 + (e & 63);
            const float* xr = x + (size_t)b * INF;
            const float* wr = w + (size_t)o * INF;
            const float* sr = s + (size_t)o * INF;
            const float* tr = t + (size_t)o * INF;
            float sum = 0.f;
            for (int i = 0; i < INF; ++i) {
                float z = (xr[i] - tr[i]) / sr[i];
                sum += wr[i] * (-z * __expf(-0.5f * z * z));
            }
            out[(size_t)b * OUTF + o] = sum;
        }
        return;
    }

    extern __shared__ char dsm[];
    const uint32_t sb = smem_u32(dsm);

    const int wid = tid >> 5, lid = tid & 31;
    const int wm = wid >> 2, wn = wid & 3;        // 2m x 4n warps, tile 16x16

    // mbarriers at sb + 16*stage; stages at sb + 1024 + stage*STAGEB
    if (tid == 0) {
        MBARRIER_INIT(sb + 0, 1);
        MBARRIER_INIT(sb + 16, 1);
        MBARRIER_INIT(sb + 32, 1);
    }
    __syncthreads();

    auto issue_load = [&](int ci) {
        const int stage = ci % NSTAGE;
        const uint32_t mbar = sb + stage * 16;
        const uint32_t st = sb + SMEM_STAGE0 + stage * STAGEB;
        MBARRIER_EXPECT_TX(mbar, STAGEB);
        bulk_g2s(st, g_phi_c + ((size_t)ci * BATCH + m0) * BK, A_TILE, mbar);
        bulk_g2s(st + A_TILE, g_w_c + ((size_t)ci * OUTF + n0) * BK, B_TILE, mbar);
    };

    if (tid == 0) { issue_load(0); issue_load(1); }

    // accumulators split by k16 parity: [kspar][nb][4] -> 4 chains/warp
    float acc[2][2][4] = {{{0}}};

    const int a_row = wm * 16 + (lid & 15);
    const int a_colq = (lid >> 4) * 8;
    const int b_row7 = (lid & 7);
    const int b_colq = (lid >> 3) * 8;           // 0,8,16,24 over k32

    // fragment double buffers
    uint32_t af[2][2][4], bf[2][2][4];

    #pragma unroll
    for (int ci = 0; ci < NCHUNK; ci++) {
        MBARRIER_WAIT_PARITY(sb + (ci % NSTAGE) * 16, (ci / NSTAGE) & 1);
        __syncthreads();   // all warps done reading stage (ci+2)%3 (iter ci-1)

        if (tid == 0 && ci + 2 < NCHUNK) issue_load(ci + 2);

        const uint32_t sA = sb + SMEM_STAGE0 + (ci % NSTAGE) * STAGEB;
        const uint32_t sB = sA + A_TILE;

        // preload frags for kh=0
        {
            #pragma unroll
            for (int nb = 0; nb < 2; nb++) {
                const int brow = wn * 16 + nb * 8 + b_row7;
                ldm_x4(bf[0][nb][0], bf[0][nb][1], bf[0][nb][2], bf[0][nb][3],
                       swz(sB, brow, b_colq));
            }
            #pragma unroll
            for (int ks = 0; ks < 2; ks++)
                ldm_x4(af[0][ks][0], af[0][ks][1], af[0][ks][2], af[0][ks][3],
                       swz(sA, a_row, ks * 16 + a_colq));
        }

        #pragma unroll
        for (int kh = 0; kh < BK / 32; kh++) {   // 4 k32 groups
            const int cb = kh & 1, nx = cb ^ 1;
            if (kh + 1 < BK / 32) {
                const int kb32n = (kh + 1) * 32;
                #pragma unroll
                for (int nb = 0; nb < 2; nb++) {
                    const int brow = wn * 16 + nb * 8 + b_row7;
                    ldm_x4(bf[nx][nb][0], bf[nx][nb][1],
                           bf[nx][nb][2], bf[nx][nb][3],
                           swz(sB, brow, kb32n + b_colq));
                }
                #pragma unroll
                for (int ks = 0; ks < 2; ks++)
                    ldm_x4(af[nx][ks][0], af[nx][ks][1],
                           af[nx][ks][2], af[nx][ks][3],
                           swz(sA, a_row, kb32n + ks * 16 + a_colq));
            }
            #pragma unroll
            for (int ks = 0; ks < 2; ks++)
                #pragma unroll
                for (int nb = 0; nb < 2; nb++)
                    mma16816(acc[ks][nb], af[cb][ks], &bf[cb][nb][ks * 2]);
        }
    }

    const int row0 = m0 + wm * 16 + (lid >> 2);
    #pragma unroll
    for (int nb = 0; nb < 2; nb++) {
        const int col = n0 + wn * 16 + nb * 8 + (lid & 3) * 2;
        *reinterpret_cast<float2*>(&out[(size_t)row0 * OUTF + col]) =
            make_float2(acc[0][nb][0] + acc[1][nb][0],
                        acc[0][nb][1] + acc[1][nb][1]);
        *reinterpret_cast<float2*>(&out[(size_t)(row0 + 8) * OUTF + col]) =
            make_float2(acc[0][nb][2] + acc[1][nb][2],
                        acc[0][nb][3] + acc[1][nb][3]);
    }
}

extern "C" void kernel_launch(void* const* d_in, const int* in_sizes, int n_in,
                              void* d_out, int out_size) {
    const float* x     = (const float*)d_in[0];
    const float* wgt   = (const float*)d_in[1];
    const float* scale = (const float*)d_in[2];
    const float* trans = (const float*)d_in[3];
    float* out = (float*)d_out;

    static bool attr_set = false;
    if (!attr_set) {
        cudaFuncSetAttribute(mma_gemm_kernel,
                             cudaFuncAttributeMaxDynamicSharedMemorySize,
                             GEMM_SMEM);
        attr_set = true;
    }

    prep_kernel<<<W_BLOCKS + PHI_BLOCKS, 256>>>(
        (const float4*)wgt, (const float4*)x,
        (const float4*)scale, (const float4*)trans);
    mma_gemm_kernel<<<dim3(OUTF / BN, BATCH / BM), 256, GEMM_SMEM>>>(
        out, x, wgt, scale, trans);
}

// round 17
// speedup vs baseline: 1.1311x; 1.1311x over previous
#include <cuda_runtime.h>
#include <cuda_fp16.h>
#include <cstdint>

#define BATCH 256
#define OUTF  1024
#define INF   1024

// ---------------- device scratch (no allocs allowed) ----------------
// chunk-major, unit-swizzled fp16 copies: [kchunk][row][128 fp16],
// 16B unit u stored at u ^ (row & 7) so a verbatim bulk copy lands
// bank-conflict-free for ldmatrix.
__device__ int g_flag = 0;   // monotonic: 0 = fast path valid
__device__ __half g_phi_c[BATCH * INF];
__device__ __half g_w_c[OUTF * INF];

// ---------------- helpers ----------------
__device__ __forceinline__ uint32_t smem_u32(const void* p) {
    uint32_t a;
    asm("{ .reg .u64 t; cvta.to.shared.u64 t, %1; cvt.u32.u64 %0, t; }"
        : "=r"(a) : "l"(p));
    return a;
}

#define MBARRIER_INIT(addr, cnt)                                                \
    asm volatile("mbarrier.init.shared.b64 [%0], %1;"                           \
                 :: "r"(addr), "r"((uint32_t)(cnt)) : "memory")

#define MBARRIER_EXPECT_TX(addr, bytes)                                         \
    asm volatile("mbarrier.arrive.expect_tx.shared.b64 _, [%0], %1;"            \
                 :: "r"(addr), "r"((uint32_t)(bytes)) : "memory")

#define MBARRIER_WAIT_PARITY(addr, parity) do {                                 \
    uint32_t _m = (uint32_t)(addr);                                             \
    uint32_t _p = (uint32_t)(parity);                                           \
    asm volatile(                                                               \
        "{\n\t.reg .pred P1;\n\t"                                               \
        "WL_%=:\n\t"                                                            \
        "mbarrier.try_wait.parity.acquire.cta.shared::cta.b64 P1, [%0], %1, 0x989680;\n\t" \
        "@P1 bra.uni WD_%=;\n\t"                                                \
        "bra.uni WL_%=;\n\t"                                                    \
        "WD_%=:\n\t}"                                                           \
        :: "r"(_m), "r"(_p) : "memory");                                        \
} while (0)

__device__ __forceinline__ void bulk_g2s(uint32_t dst, const void* src,
                                         uint32_t bytes, uint32_t mbar) {
    asm volatile(
        "cp.async.bulk.shared::cluster.global.mbarrier::complete_tx::bytes "
        "[%0], [%1], %2, [%3];"
        :: "r"(dst), "l"(src), "r"(bytes), "r"(mbar) : "memory");
}

__device__ __forceinline__ void ldm_x4(uint32_t& r0, uint32_t& r1,
                                       uint32_t& r2, uint32_t& r3,
                                       uint32_t addr) {
    asm volatile("ldmatrix.sync.aligned.m8n8.x4.shared.b16 {%0,%1,%2,%3}, [%4];"
                 : "=r"(r0), "=r"(r1), "=r"(r2), "=r"(r3) : "r"(addr));
}

__device__ __forceinline__ void mma16816(float* c, const uint32_t* a,
                                         const uint32_t* b) {
    asm volatile(
        "mma.sync.aligned.m16n8k16.row.col.f32.f16.f16.f32 "
        "{%0,%1,%2,%3}, {%4,%5,%6,%7}, {%8,%9}, {%0,%1,%2,%3};"
        : "+f"(c[0]), "+f"(c[1]), "+f"(c[2]), "+f"(c[3])
        : "r"(a[0]), "r"(a[1]), "r"(a[2]), "r"(a[3]), "r"(b[0]), "r"(b[1]));
}

// pack 8 floats -> uint4 of fp16 (rn)
__device__ __forceinline__ uint4 pack8_h(const float4& a, const float4& b) {
    __half2 h0 = __floats2half2_rn(a.x, a.y);
    __half2 h1 = __floats2half2_rn(a.z, a.w);
    __half2 h2 = __floats2half2_rn(b.x, b.y);
    __half2 h3 = __floats2half2_rn(b.z, b.w);
    return make_uint4(*(uint32_t*)&h0, *(uint32_t*)&h1,
                      *(uint32_t*)&h2, *(uint32_t*)&h3);
}

__device__ __forceinline__ float dog(float x, float t, float s) {
    float z = (x - t) / s;
    return -z * __expf(-0.5f * z * z);
}

// ---------------- fused prep: check + W/phi -> fp16 chunk-major ----------
#define W_BLOCKS   ((OUTF * INF / 8) / 256)    // 512
#define PHI_BLOCKS ((BATCH * INF / 8) / 256)   // 128

__global__ __launch_bounds__(256)
void prep_kernel(const float4* __restrict__ w,
                 const float4* __restrict__ x,
                 const float4* __restrict__ scale,
                 const float4* __restrict__ trans) {
    if (blockIdx.x < W_BLOCKS) {
        int tix = blockIdx.x * 256 + threadIdx.x;   // 0..131071, 8 elems each
        int j = tix * 2;                             // even float4 index
        int i40 = j & (INF / 4 - 1);
        int i41 = (j + 1) & (INF / 4 - 1);

        float4 w0 = w[j],     w1 = w[j + 1];
        float4 s0 = scale[j], s1 = scale[j + 1];
        float4 t0 = trans[j], t1 = trans[j + 1];
        float4 rs0 = scale[i40], rs1 = scale[i41];
        float4 rt0 = trans[i40], rt1 = trans[i41];

        bool bad =
            (s0.x != rs0.x) | (s0.y != rs0.y) | (s0.z != rs0.z) | (s0.w != rs0.w) |
            (s1.x != rs1.x) | (s1.y != rs1.y) | (s1.z != rs1.z) | (s1.w != rs1.w) |
            (t0.x != rt0.x) | (t0.y != rt0.y) | (t0.z != rt0.z) | (t0.w != rt0.w) |
            (t1.x != rt1.x) | (t1.y != rt1.y) | (t1.z != rt1.z) | (t1.w != rt1.w);
        if (bad) atomicOr(&g_flag, 1);

        int o = tix >> 7;             // row 0..1023
        int ug = tix & 127;           // 16B unit within row (global k)
        int chunk = ug >> 4;          // k-chunk 0..7
        int u = ug & 15;              // unit within chunk
        int dst = (chunk * OUTF + o) * 16 + (u ^ (o & 7));
        reinterpret_cast<uint4*>(g_w_c)[dst] = pack8_h(w0, w1);
    } else {
        int tix = (blockIdx.x - W_BLOCKS) * 256 + threadIdx.x;  // 0..32767
        int j = tix * 2;
        int i40 = j & (INF / 4 - 1);
        int i41 = (j + 1) & (INF / 4 - 1);
        float4 x0 = x[j], x1 = x[j + 1];
        float4 s0 = scale[i40], s1 = scale[i41];
        float4 t0 = trans[i40], t1 = trans[i41];
        float4 p0, p1;
        p0.x = dog(x0.x, t0.x, s0.x);
        p0.y = dog(x0.y, t0.y, s0.y);
        p0.z = dog(x0.z, t0.z, s0.z);
        p0.w = dog(x0.w, t0.w, s0.w);
        p1.x = dog(x1.x, t1.x, s1.x);
        p1.y = dog(x1.y, t1.y, s1.y);
        p1.z = dog(x1.z, t1.z, s1.z);
        p1.w = dog(x1.w, t1.w, s1.w);

        int m = tix >> 7;             // row 0..255
        int ug = tix & 127;
        int chunk = ug >> 4;
        int u = ug & 15;
        int dst = (chunk * BATCH + m) * 16 + (u ^ (m & 7));
        reinterpret_cast<uint4*>(g_phi_c)[dst] = pack8_h(p0, p1);
    }
}

// ---------------- fp16 mma.sync GEMM, all-upfront bulk loads -------------
// out(256,1024) = phi @ W^T. CTA tile 32x64, 256 threads (8 warps, 2m x 4n),
// warp tile 16x16. 8 chunks, EIGHT stages (no recycling): all 16 bulk
// copies issued at kernel start; mainloop = wait mbar + compute. No
// __syncthreads, no per-chunk issue, no stage hazards.
#define BM 32
#define BN 64
#define BK 128
#define NCHUNK (INF / BK)            // 8
#define ROWB    256                  // 128 fp16, no pad (XOR swizzle)
#define A_TILE  (BM * ROWB)          // 8192
#define B_TILE  (BN * ROWB)          // 16384
#define STAGEB  (A_TILE + B_TILE)    // 24576
#define SMEM_STAGE0 1024
#define GEMM_SMEM (SMEM_STAGE0 + NCHUNK * STAGEB)   // 197632 (~193KB)

// swizzled smem address for 16B-aligned (row, kElem) within a tile
__device__ __forceinline__ uint32_t swz(uint32_t base, int row, int kElem) {
    return base + row * ROWB + (((kElem >> 3) ^ (row & 7)) << 4);
}

__global__ __launch_bounds__(256, 1)
void mma_gemm_kernel(float* __restrict__ out,
                     const float* __restrict__ x,
                     const float* __restrict__ w,
                     const float* __restrict__ s,
                     const float* __restrict__ t) {
    const int tid = threadIdx.x;
    const int m0 = blockIdx.y * BM;
    const int n0 = blockIdx.x * BN;

    if (g_flag) {
        // exact general path: 8 outputs per thread
        for (int e = tid; e < BM * BN; e += 256) {
            int b = m0 + (e >> 6);
            int o = n0 + (e & 63);
            const float* xr = x + (size_t)b * INF;
            const float* wr = w + (size_t)o * INF;
            const float* sr = s + (size_t)o * INF;
            const float* tr = t + (size_t)o * INF;
            float sum = 0.f;
            for (int i = 0; i < INF; ++i) {
                float z = (xr[i] - tr[i]) / sr[i];
                sum += wr[i] * (-z * __expf(-0.5f * z * z));
            }
            out[(size_t)b * OUTF + o] = sum;
        }
        return;
    }

    extern __shared__ char dsm[];
    const uint32_t sb = smem_u32(dsm);

    const int wid = tid >> 5, lid = tid & 31;
    const int wm = wid >> 2, wn = wid & 3;        // 2m x 4n warps, tile 16x16

    // 8 mbarriers at sb + 16*ci; stages at sb + 1024 + ci*STAGEB
    if (tid == 0) {
        #pragma unroll
        for (int ci = 0; ci < NCHUNK; ci++) MBARRIER_INIT(sb + ci * 16, 1);
    }
    __syncthreads();

    // issue ALL chunk loads up front (16 bulk copies, one thread)
    if (tid == 0) {
        #pragma unroll
        for (int ci = 0; ci < NCHUNK; ci++) {
            const uint32_t mbar = sb + ci * 16;
            const uint32_t st = sb + SMEM_STAGE0 + ci * STAGEB;
            MBARRIER_EXPECT_TX(mbar, STAGEB);
            bulk_g2s(st, g_phi_c + ((size_t)ci * BATCH + m0) * BK,
                     A_TILE, mbar);
            bulk_g2s(st + A_TILE, g_w_c + ((size_t)ci * OUTF + n0) * BK,
                     B_TILE, mbar);
        }
    }

    // accumulators split by k16 parity: [kspar][nb][4] -> 4 chains/warp
    float acc[2][2][4] = {{{0}}};

    const int a_row = wm * 16 + (lid & 15);
    const int a_colq = (lid >> 4) * 8;
    const int b_row7 = (lid & 7);
    const int b_colq = (lid >> 3) * 8;           // 0,8,16,24 over k32

    // fragment double buffers
    uint32_t af[2][2][4], bf[2][2][4];

    #pragma unroll
    for (int ci = 0; ci < NCHUNK; ci++) {
        MBARRIER_WAIT_PARITY(sb + ci * 16, 0);   // single-use: parity 0

        const uint32_t sA = sb + SMEM_STAGE0 + ci * STAGEB;
        const uint32_t sB = sA + A_TILE;

        // preload frags for kh=0
        {
            #pragma unroll
            for (int nb = 0; nb < 2; nb++) {
                const int brow = wn * 16 + nb * 8 + b_row7;
                ldm_x4(bf[0][nb][0], bf[0][nb][1], bf[0][nb][2], bf[0][nb][3],
                       swz(sB, brow, b_colq));
            }
            #pragma unroll
            for (int ks = 0; ks < 2; ks++)
                ldm_x4(af[0][ks][0], af[0][ks][1], af[0][ks][2], af[0][ks][3],
                       swz(sA, a_row, ks * 16 + a_colq));
        }

        #pragma unroll
        for (int kh = 0; kh < BK / 32; kh++) {   // 4 k32 groups
            const int cb = kh & 1, nx = cb ^ 1;
            if (kh + 1 < BK / 32) {
                const int kb32n = (kh + 1) * 32;
                #pragma unroll
                for (int nb = 0; nb < 2; nb++) {
                    const int brow = wn * 16 + nb * 8 + b_row7;
                    ldm_x4(bf[nx][nb][0], bf[nx][nb][1],
                           bf[nx][nb][2], bf[nx][nb][3],
                           swz(sB, brow, kb32n + b_colq));
                }
                #pragma unroll
                for (int ks = 0; ks < 2; ks++)
                    ldm_x4(af[nx][ks][0], af[nx][ks][1],
                           af[nx][ks][2], af[nx][ks][3],
                           swz(sA, a_row, kb32n + ks * 16 + a_colq));
            }
            #pragma unroll
            for (int ks = 0; ks < 2; ks++)
                #pragma unroll
                for (int nb = 0; nb < 2; nb++)
                    mma16816(acc[ks][nb], af[cb][ks], &bf[cb][nb][ks * 2]);
        }
    }

    const int row0 = m0 + wm * 16 + (lid >> 2);
    #pragma unroll
    for (int nb = 0; nb < 2; nb++) {
        const int col = n0 + wn * 16 + nb * 8 + (lid & 3) * 2;
        *reinterpret_cast<float2*>(&out[(size_t)row0 * OUTF + col]) =
            make_float2(acc[0][nb][0] + acc[1][nb][0],
                        acc[0][nb][1] + acc[1][nb][1]);
        *reinterpret_cast<float2*>(&out[(size_t)(row0 + 8) * OUTF + col]) =
            make_float2(acc[0][nb][2] + acc[1][nb][2],
                        acc[0][nb][3] + acc[1][nb][3]);
    }
}

extern "C" void kernel_launch(void* const* d_in, const int* in_sizes, int n_in,
                              void* d_out, int out_size) {
    const float* x     = (const float*)d_in[0];
    const float* wgt   = (const float*)d_in[1];
    const float* scale = (const float*)d_in[2];
    const float* trans = (const float*)d_in[3];
    float* out = (float*)d_out;

    static bool attr_set = false;
    if (!attr_set) {
        cudaFuncSetAttribute(mma_gemm_kernel,
                             cudaFuncAttributeMaxDynamicSharedMemorySize,
                             GEMM_SMEM);
        attr_set = true;
    }

    prep_kernel<<<W_BLOCKS + PHI_BLOCKS, 256>>>(
        (const float4*)wgt, (const float4*)x,
        (const float4*)scale, (const float4*)trans);
    mma_gemm_kernel<<<dim3(OUTF / BN, BATCH / BM), 256, GEMM_SMEM>>>(
        out, x, wgt, scale, trans);
}